// round 9
// baseline (speedup 1.0000x reference)
#include <cuda_runtime.h>
#include <cuda_pipeline.h>

#define NN    8192
#define DD    64
#define HH    4096
#define SS    2          // samples per block
#define TPS   256        // threads per sample
#define NP    8          // hidden-unit pairs per thread (16 units)
#define BLOCK 512
#define NB    4          // W1 ring rows (2-row groups, sync every 2 steps)

typedef unsigned long long u64;

static __device__ __forceinline__ u64 pk(float lo, float hi) {
    u64 r; asm("mov.b64 %0,{%1,%2};" : "=l"(r) : "f"(lo), "f"(hi)); return r;
}
static __device__ __forceinline__ void upk(float& lo, float& hi, u64 v) {
    asm("mov.b64 {%0,%1},%2;" : "=f"(lo), "=f"(hi) : "l"(v));
}
static __device__ __forceinline__ u64 fma2(u64 a, u64 b, u64 c) {
    u64 d; asm("fma.rn.f32x2 %0,%1,%2,%3;" : "=l"(d) : "l"(a), "l"(b), "l"(c)); return d;
}
static __device__ __forceinline__ u64 mul2(u64 a, u64 b) {
    u64 d; asm("mul.rn.f32x2 %0,%1,%2;" : "=l"(d) : "l"(a), "l"(b)); return d;
}
static __device__ __forceinline__ float frsq(float x) {
    float r; asm("rsqrt.approx.f32 %0,%1;" : "=f"(r) : "f"(x)); return r;
}
static __device__ __forceinline__ float frcp(float x) {
    float r; asm("rcp.approx.f32 %0,%1;" : "=f"(r) : "f"(x)); return r;
}
static __device__ __forceinline__ float fex2(float x) {
    float r; asm("ex2.approx.f32 %0,%1;" : "=f"(r) : "f"(x)); return r;
}
static __device__ __forceinline__ float ftanh(float x) {
    float e = __expf(2.0f * x);
    return 1.0f - __fdividef(2.0f, e + 1.0f);
}
// MUFU-path packed tanh: t = 1 - 2/(1 + e^{2x}); robust at +/-inf.
static __device__ __forceinline__ u64 tanh2_ex2(u64 hA) {
    float h0, h1; upk(h0, h1, hA);
    float e0 = fex2(h0 * 2.8853901817f);
    float e1 = fex2(h1 * 2.8853901817f);
    float t0 = fmaf(-2.0f, frcp(e0 + 1.0f), 1.0f);
    float t1 = fmaf(-2.0f, frcp(e1 + 1.0f), 1.0f);
    return pk(t0, t1);
}

// smem: W1 ring + packed W2 + spins + partials + products
#define SW2_U 1024                       // ulonglong2 entries per m-plane
#define SMEM_BYTES (NB*HH*4 + 2*SW2_U*16 + SS*DD*4 + DD*SS*8*8 + SS*2*4)

__global__ void __launch_bounds__(BLOCK, 2)
qnade_kernel(const float* __restrict__ gx,  const float* __restrict__ gW1,
             const float* __restrict__ gb1, const float* __restrict__ gW2,
             const float* __restrict__ gb2, float* __restrict__ gout)
{
    extern __shared__ char sm_[];
    float*      sW1   = (float*)sm_;                        // [NB][HH] ring
    ulonglong2* sW2   = (ulonglong2*)(sW1 + NB * HH);       // [2][1024] (m-major)
    float*      sX    = (float*)(sW2 + 2 * SW2_U);          // [SS][DD]
    float2*     sPart = (float2*)(sX + SS * DD);            // [DD][SS][8]
    float*      sProd = (float*)(sPart + DD * SS * 8);      // [SS][2]

    const int tid  = threadIdx.x;
    const int s    = tid >> 8;       // sample within block (0..1)
    const int wg   = tid & 255;      // thread within sample group
    const int wis  = wg >> 5;        // warp within sample group (0..7)
    const int lane = tid & 31;
    const int n    = blockIdx.x * SS + s;

    for (int i = tid; i < SS * DD; i += BLOCK)
        sX[i] = gx[blockIdx.x * SS * DD + i];

    // stage W2 pre-transposed: entry (m, f4) <- gW2 float4 index p = 2*f4+m
    // holds {pk(w0_even, w0_odd), pk(w1_even, w1_odd)} for unit pair 2p,2p+1
    {
        const float4* w2v = (const float4*)gW2;             // [H,2] -> 2048 float4
        for (int p = tid; p < 2 * SW2_U; p += BLOCK) {
            float4 w = w2v[p];
            ulonglong2 e;
            e.x = pk(w.x, w.z);   // W2 column 0 pair
            e.y = pk(w.y, w.w);   // W2 column 1 pair
            sW2[((p & 1) << 10) + (p >> 1)] = e;
        }
    }

    // prefetch W1 rows 0,1
    {
        const float4* src = (const float4*)gW1;
        float4* d0 = (float4*)(sW1 + 0 * HH);
        float4* d1 = (float4*)(sW1 + 1 * HH);
        for (int i = tid; i < HH / 4; i += BLOCK) {
            __pipeline_memcpy_async(d0 + i, src + i, 16);
            __pipeline_memcpy_async(d1 + i, src + HH / 4 + i, 16);
        }
        __pipeline_commit();
    }

    // persistent packed state: thread wg owns units 4*f4..4*f4+3, f4 = wg+256*k4
    u64 hp[NP];
    {
        const ulonglong2* b1v = (const ulonglong2*)gb1;
#pragma unroll
        for (int k4 = 0; k4 < NP / 2; k4++) {
            ulonglong2 b = b1v[wg + 256 * k4];
            hp[2*k4+0] = b.x; hp[2*k4+1] = b.y;
        }
    }
    const u64 C4  = pk(2.75573192e-6f, 2.75573192e-6f);
    const u64 C3  = pk(1.98412698e-4f, 1.98412698e-4f);
    const u64 C2  = pk(8.33333333e-3f, 8.33333333e-3f);
    const u64 C1  = pk(1.66666667e-1f, 1.66666667e-1f);
    const u64 ONE = pk(1.0f, 1.0f);

    for (int it = 0; it < DD / 2; it++) {
        __pipeline_wait_prior(0);   // group `it` (rows 2it,2it+1) arrived
        __syncthreads();            // visible; old readers of target slots done
        {   // prefetch rows 2it+2, 2it+3 -> slots disjoint from read slots
            const int r0 = 2 * it + 2, r1 = 2 * it + 3;
            if (r1 < DD) {
                const float4* s0 = (const float4*)(gW1 + (size_t)r0 * HH);
                const float4* s1 = (const float4*)(gW1 + (size_t)r1 * HH);
                float4* d0 = (float4*)(sW1 + (r0 % NB) * HH);
                float4* d1 = (float4*)(sW1 + (r1 % NB) * HH);
                for (int i = tid; i < HH / 4; i += BLOCK) {
                    __pipeline_memcpy_async(d0 + i, s0 + i, 16);
                    __pipeline_memcpy_async(d1 + i, s1 + i, 16);
                }
            }
            __pipeline_commit();
        }

#pragma unroll
        for (int half = 0; half < 2; half++) {
            const int d = 2 * it + half;
            const float xd = sX[s * DD + d];
            const u64 xdp = pk(xd, xd);
            const ulonglong2* w1v = (const ulonglong2*)(sW1 + (d % NB) * HH);
            u64 a0p = 0ull, a1p = 0ull;
#pragma unroll
            for (int k4 = 0; k4 < NP / 2; k4++) {
                const int f4 = wg + 256 * k4;
                ulonglong2 wp = w1v[f4];                  // conflict-free LDS.128
#pragma unroll
                for (int m = 0; m < 2; m++) {
                    const int q = 2 * k4 + m;
                    ulonglong2 w2e = sW2[(m << 10) + f4]; // conflict-free LDS.128
                    u64 hA = hp[q];
                    u64 t;
                    if ((q & 3) == 0) {
                        t = tanh2_ex2(hA);                // MUFU path, 2 of 8 pairs
                    } else {
                        u64 y = mul2(hA, hA);             // FMA path: s*rsqrt(1+s^2)
                        u64 p = fma2(C4, y, C3);
                        p = fma2(p, y, C2);
                        p = fma2(p, y, C1);
                        p = fma2(p, y, ONE);
                        u64 sv = mul2(p, hA);
                        u64 dd2 = fma2(sv, sv, ONE);
                        float dl, dh; upk(dl, dh, dd2);
                        t = mul2(sv, pk(frsq(dl), frsq(dh)));
                    }
                    a0p = fma2(t, w2e.x, a0p);
                    a1p = fma2(t, w2e.y, a1p);
                    hp[q] = fma2(xdp, (m == 0) ? wp.x : wp.y, hA);
                }
            }
            float a0l, a0h, a1l, a1h;
            upk(a0l, a0h, a0p); upk(a1l, a1h, a1p);
            float a0 = a0l + a0h, a1 = a1l + a1h;
#pragma unroll
            for (int off = 16; off; off >>= 1) {
                a0 += __shfl_xor_sync(0xffffffffu, a0, off);
                a1 += __shfl_xor_sync(0xffffffffu, a1, off);
            }
            if (lane == 0) sPart[(d * SS + s) * 8 + wis] = make_float2(a0, a1);
        }
    }

    // deferred head: threads wg<64 each finish one step d, then product-reduce
    __syncthreads();
    const float b20 = gb2[0], b21 = gb2[1];
    if (wg < DD) {
        const int d = wg;
        float z0 = b20, z1 = b21;
#pragma unroll
        for (int w = 0; w < 8; w++) {
            float2 v = sPart[(d * SS + s) * 8 + w];
            z0 += v.x; z1 += v.y;
        }
        float o0 = ftanh(z0), o1 = ftanh(z1);
        float nrm = fmaxf(sqrtf(o0 * o0 + o1 * o1), 1e-12f);
        float sel = (sX[s * DD + d] > 0.0f ? o0 : o1) / nrm;
#pragma unroll
        for (int off = 16; off; off >>= 1)
            sel *= __shfl_xor_sync(0xffffffffu, sel, off);
        if (lane == 0) sProd[s * 2 + wis] = sel;   // wis = 0,1 only (wg<64)
    }
    __syncthreads();
    if (wg == 0) gout[n] = sProd[s * 2 + 0] * sProd[s * 2 + 1];
}

extern "C" void kernel_launch(void* const* d_in, const int* in_sizes, int n_in,
                              void* d_out, int out_size) {
    const float* x  = (const float*)d_in[0];
    const float* W1 = (const float*)d_in[1];
    const float* b1 = (const float*)d_in[2];
    const float* W2 = (const float*)d_in[3];
    const float* b2 = (const float*)d_in[4];
    cudaFuncSetAttribute(qnade_kernel,
                         cudaFuncAttributeMaxDynamicSharedMemorySize, SMEM_BYTES);
    qnade_kernel<<<NN / SS, BLOCK, SMEM_BYTES>>>(x, W1, b1, W2, b2, (float*)d_out);
}

// round 10
// speedup vs baseline: 1.1187x; 1.1187x over previous
#include <cuda_runtime.h>

#define NN    8192
#define DD    64
#define HH    4096
#define SS    2          // samples per block
#define NP    8          // hidden-unit pairs per thread (16 units)
#define BLOCK 512

typedef unsigned long long u64;

static __device__ __forceinline__ u64 pk(float lo, float hi) {
    u64 r; asm("mov.b64 %0,{%1,%2};" : "=l"(r) : "f"(lo), "f"(hi)); return r;
}
static __device__ __forceinline__ void upk(float& lo, float& hi, u64 v) {
    asm("mov.b64 {%0,%1},%2;" : "=f"(lo), "=f"(hi) : "l"(v));
}
static __device__ __forceinline__ u64 fma2(u64 a, u64 b, u64 c) {
    u64 d; asm("fma.rn.f32x2 %0,%1,%2,%3;" : "=l"(d) : "l"(a), "l"(b), "l"(c)); return d;
}
static __device__ __forceinline__ u64 mul2(u64 a, u64 b) {
    u64 d; asm("mul.rn.f32x2 %0,%1,%2;" : "=l"(d) : "l"(a), "l"(b)); return d;
}
static __device__ __forceinline__ float frsq(float x) {
    float r; asm("rsqrt.approx.f32 %0,%1;" : "=f"(r) : "f"(x)); return r;
}
static __device__ __forceinline__ float frcp(float x) {
    float r; asm("rcp.approx.f32 %0,%1;" : "=f"(r) : "f"(x)); return r;
}
static __device__ __forceinline__ float fex2(float x) {
    float r; asm("ex2.approx.f32 %0,%1;" : "=f"(r) : "f"(x)); return r;
}
static __device__ __forceinline__ float ftanh(float x) {
    float e = __expf(2.0f * x);
    return 1.0f - __fdividef(2.0f, e + 1.0f);
}
// MUFU-path packed tanh: t = 1 - 2/(1 + e^{2x}); robust at +/-inf.
static __device__ __forceinline__ u64 tanh2_ex2(u64 hA) {
    float h0, h1; upk(h0, h1, hA);
    float e0 = fex2(h0 * 2.8853901817f);
    float e1 = fex2(h1 * 2.8853901817f);
    float t0 = fmaf(-2.0f, frcp(e0 + 1.0f), 1.0f);
    float t1 = fmaf(-2.0f, frcp(e1 + 1.0f), 1.0f);
    return pk(t0, t1);
}
// FMA-path packed tanh: t = s*rsqrt(1+s^2), s = h*P(h^2) (deg-4 sinh Taylor)
static __device__ __forceinline__ u64 tanh2_fma(u64 hA) {
    const u64 C4  = pk(2.75573192e-6f, 2.75573192e-6f);
    const u64 C3  = pk(1.98412698e-4f, 1.98412698e-4f);
    const u64 C2  = pk(8.33333333e-3f, 8.33333333e-3f);
    const u64 C1  = pk(1.66666667e-1f, 1.66666667e-1f);
    const u64 ONE = pk(1.0f, 1.0f);
    u64 y = mul2(hA, hA);
    u64 p = fma2(C4, y, C3);
    p = fma2(p, y, C2);
    p = fma2(p, y, C1);
    p = fma2(p, y, ONE);
    u64 sv = mul2(p, hA);
    u64 dd2 = fma2(sv, sv, ONE);
    float dl, dh; upk(dl, dh, dd2);
    return mul2(sv, pk(frsq(dl), frsq(dh)));
}

// smem: packed W2 + spins + partials + products (NO W1 ring -> W1 lives in L1)
#define SW2_U 1024                       // ulonglong2 entries per m-plane
#define SMEM_BYTES (2*SW2_U*16 + SS*DD*4 + DD*SS*8*8 + SS*2*4)

__global__ void __launch_bounds__(BLOCK, 2)
qnade_kernel(const float* __restrict__ gx,  const float* __restrict__ gW1,
             const float* __restrict__ gb1, const float* __restrict__ gW2,
             const float* __restrict__ gb2, float* __restrict__ gout)
{
    extern __shared__ char sm_[];
    ulonglong2* sW2   = (ulonglong2*)sm_;                   // [2][1024] (m-major)
    float*      sX    = (float*)(sW2 + 2 * SW2_U);          // [SS][DD]
    float2*     sPart = (float2*)(sX + SS * DD);            // [DD][SS][8]
    float*      sProd = (float*)(sPart + DD * SS * 8);      // [SS][2]

    const int tid  = threadIdx.x;
    const int s    = tid >> 8;       // sample within block (0..1)
    const int wg   = tid & 255;      // thread within sample group
    const int wis  = wg >> 5;        // warp within sample group (0..7)
    const int lane = tid & 31;
    const int n    = blockIdx.x * SS + s;

    for (int i = tid; i < SS * DD; i += BLOCK)
        sX[i] = gx[blockIdx.x * SS * DD + i];

    // stage W2 pre-transposed: float4 p = 2*f4+m -> plane m, entry f4:
    // {pk(w0_even,w0_odd), pk(w1_even,w1_odd)} for unit pair 2p,2p+1
    {
        const float4* w2v = (const float4*)gW2;             // [H,2] -> 2048 float4
        for (int p = tid; p < 2 * SW2_U; p += BLOCK) {
            float4 w = w2v[p];
            ulonglong2 e;
            e.x = pk(w.x, w.z);
            e.y = pk(w.y, w.w);
            sW2[((p & 1) << 10) + (p >> 1)] = e;
        }
    }

    // persistent packed state: thread wg owns units 4*f4..4*f4+3, f4 = wg+256*k4
    u64 hp[NP];
    {
        const ulonglong2* b1v = (const ulonglong2*)gb1;
#pragma unroll
        for (int k4 = 0; k4 < NP / 2; k4++) {
            ulonglong2 b = b1v[wg + 256 * k4];
            hp[2*k4+0] = b.x; hp[2*k4+1] = b.y;
        }
    }
    __syncthreads();   // sW2 / sX staged

    for (int ds = 0; ds < DD; ds += 2) {
        if ((ds & 7) == 0) __syncthreads();   // drift control: keep warps within
                                              // a few W1 rows so L1 stays hot
        const float xd0 = sX[s * DD + ds];
        const float xd1 = sX[s * DD + ds + 1];
        const u64 x0p = pk(xd0, xd0);
        const u64 x1p = pk(xd1, xd1);
        const ulonglong2* w1a = (const ulonglong2*)(gW1 + (size_t)ds * HH);
        const ulonglong2* w1b = (const ulonglong2*)(gW1 + (size_t)(ds + 1) * HH);

        u64 p00 = 0ull, p01 = 0ull;   // step ds   dots (packed even/odd)
        u64 p10 = 0ull, p11 = 0ull;   // step ds+1 dots
#pragma unroll
        for (int k4 = 0; k4 < NP / 2; k4++) {
            const int f4 = wg + 256 * k4;
            ulonglong2 wA  = w1a[f4];               // LDG.128, L1-hot
            ulonglong2 wB  = w1b[f4];
            ulonglong2 w2a = sW2[f4];               // m=0, conflict-free LDS.128
            ulonglong2 w2b = sW2[SW2_U + f4];       // m=1
#pragma unroll
            for (int m = 0; m < 2; m++) {
                const int q = 2 * k4 + m;
                const ulonglong2 w2 = m ? w2b : w2a;
                u64 hA = hp[q];
                u64 t0 = ((q & 3) == 0) ? tanh2_ex2(hA) : tanh2_fma(hA);
                p00 = fma2(t0, w2.x, p00);
                p01 = fma2(t0, w2.y, p01);
                hA = fma2(x0p, m ? wA.y : wA.x, hA);
                u64 t1 = ((q & 3) == 0) ? tanh2_ex2(hA) : tanh2_fma(hA);
                p10 = fma2(t1, w2.x, p10);
                p11 = fma2(t1, w2.y, p11);
                hp[q] = fma2(x1p, m ? wB.y : wB.x, hA);
            }
        }
        // fold packed accumulators, scalar warp reduce (both steps)
        float u, v;
        upk(u, v, p00); float a00 = u + v;
        upk(u, v, p01); float a01 = u + v;
        upk(u, v, p10); float a10 = u + v;
        upk(u, v, p11); float a11 = u + v;
#pragma unroll
        for (int off = 16; off; off >>= 1) {
            a00 += __shfl_xor_sync(0xffffffffu, a00, off);
            a01 += __shfl_xor_sync(0xffffffffu, a01, off);
            a10 += __shfl_xor_sync(0xffffffffu, a10, off);
            a11 += __shfl_xor_sync(0xffffffffu, a11, off);
        }
        if (lane == 0) {
            sPart[((ds    ) * SS + s) * 8 + wis] = make_float2(a00, a01);
            sPart[((ds + 1) * SS + s) * 8 + wis] = make_float2(a10, a11);
        }
    }

    // deferred head: threads wg<64 each finish one step d, then product-reduce
    __syncthreads();
    const float b20 = gb2[0], b21 = gb2[1];
    if (wg < DD) {
        const int d = wg;
        float z0 = b20, z1 = b21;
#pragma unroll
        for (int w = 0; w < 8; w++) {
            float2 v2 = sPart[(d * SS + s) * 8 + w];
            z0 += v2.x; z1 += v2.y;
        }
        float o0 = ftanh(z0), o1 = ftanh(z1);
        float nrm = fmaxf(sqrtf(o0 * o0 + o1 * o1), 1e-12f);
        float sel = (sX[s * DD + d] > 0.0f ? o0 : o1) / nrm;
#pragma unroll
        for (int off = 16; off; off >>= 1)
            sel *= __shfl_xor_sync(0xffffffffu, sel, off);
        if (lane == 0) sProd[s * 2 + wis] = sel;   // wis = 0,1 only (wg<64)
    }
    __syncthreads();
    if (wg == 0) gout[n] = sProd[s * 2 + 0] * sProd[s * 2 + 1];
}

extern "C" void kernel_launch(void* const* d_in, const int* in_sizes, int n_in,
                              void* d_out, int out_size) {
    const float* x  = (const float*)d_in[0];
    const float* W1 = (const float*)d_in[1];
    const float* b1 = (const float*)d_in[2];
    const float* W2 = (const float*)d_in[3];
    const float* b2 = (const float*)d_in[4];
    cudaFuncSetAttribute(qnade_kernel,
                         cudaFuncAttributeMaxDynamicSharedMemorySize, SMEM_BYTES);
    qnade_kernel<<<NN / SS, BLOCK, SMEM_BYTES>>>(x, W1, b1, W2, b2, (float*)d_out);
}

// round 12
// speedup vs baseline: 1.2043x; 1.0765x over previous
#include <cuda_runtime.h>

#define NN    8192
#define DD    64
#define HH    4096
#define SS    2          // samples per block
#define NP    8          // hidden-unit pairs per thread (16 units)
#define BLOCK 512

typedef unsigned long long u64;

static __device__ __forceinline__ u64 pk(float lo, float hi) {
    u64 r; asm("mov.b64 %0,{%1,%2};" : "=l"(r) : "f"(lo), "f"(hi)); return r;
}
static __device__ __forceinline__ void upk(float& lo, float& hi, u64 v) {
    asm("mov.b64 {%0,%1},%2;" : "=f"(lo), "=f"(hi) : "l"(v));
}
static __device__ __forceinline__ u64 fma2(u64 a, u64 b, u64 c) {
    u64 d; asm("fma.rn.f32x2 %0,%1,%2,%3;" : "=l"(d) : "l"(a), "l"(b), "l"(c)); return d;
}
static __device__ __forceinline__ u64 mul2(u64 a, u64 b) {
    u64 d; asm("mul.rn.f32x2 %0,%1,%2;" : "=l"(d) : "l"(a), "l"(b)); return d;
}
static __device__ __forceinline__ float frsq(float x) {
    float r; asm("rsqrt.approx.f32 %0,%1;" : "=f"(r) : "f"(x)); return r;
}
static __device__ __forceinline__ float frcp(float x) {
    float r; asm("rcp.approx.f32 %0,%1;" : "=f"(r) : "f"(x)); return r;
}
static __device__ __forceinline__ float fex2(float x) {
    float r; asm("ex2.approx.f32 %0,%1;" : "=f"(r) : "f"(x)); return r;
}
static __device__ __forceinline__ float ftanh(float x) {
    float e = __expf(2.0f * x);
    return 1.0f - __fdividef(2.0f, e + 1.0f);
}
// MUFU-path packed tanh: t = 1 - 2/(1 + e^{2x}); robust at +/-inf.
static __device__ __forceinline__ u64 tanh2_ex2(u64 hA) {
    float h0, h1; upk(h0, h1, hA);
    float e0 = fex2(h0 * 2.8853901817f);
    float e1 = fex2(h1 * 2.8853901817f);
    float t0 = fmaf(-2.0f, frcp(e0 + 1.0f), 1.0f);
    float t1 = fmaf(-2.0f, frcp(e1 + 1.0f), 1.0f);
    return pk(t0, t1);
}
// FMA-path packed tanh: t = s*rsqrt(1+s^2), s = h*P(h^2) (deg-3 sinh Taylor)
static __device__ __forceinline__ u64 tanh2_fma(u64 hA) {
    const u64 C3  = pk(1.98412698e-4f, 1.98412698e-4f);   // 1/7!
    const u64 C2  = pk(8.33333333e-3f, 8.33333333e-3f);   // 1/5!
    const u64 C1  = pk(1.66666667e-1f, 1.66666667e-1f);   // 1/3!
    const u64 ONE = pk(1.0f, 1.0f);
    u64 y = mul2(hA, hA);
    u64 p = fma2(C3, y, C2);
    p = fma2(p, y, C1);
    p = fma2(p, y, ONE);
    u64 sv = mul2(p, hA);
    u64 dd2 = fma2(sv, sv, ONE);
    float dl, dh; upk(dl, dh, dd2);
    return mul2(sv, pk(frsq(dl), frsq(dh)));
}

// smem: packed W2 + spins + partials + products (W1 lives in L1 via LDG)
#define SW2_U 1024                       // ulonglong2 entries per m-plane
#define NPW   32                         // partials per (step, sample): 8 warps x 4 lanes
#define SMEM_BYTES (2*SW2_U*16 + SS*DD*4 + DD*SS*NPW*8 + SS*2*4)

__global__ void __launch_bounds__(BLOCK, 2)
qnade_kernel(const float* __restrict__ gx,  const float* __restrict__ gW1,
             const float* __restrict__ gb1, const float* __restrict__ gW2,
             const float* __restrict__ gb2, float* __restrict__ gout)
{
    extern __shared__ char sm_[];
    ulonglong2* sW2   = (ulonglong2*)sm_;                   // [2][1024] (m-major)
    float*      sX    = (float*)(sW2 + 2 * SW2_U);          // [SS][DD]
    float2*     sPart = (float2*)(sX + SS * DD);            // [DD][SS][NPW]
    float*      sProd = (float*)(sPart + DD * SS * NPW);    // [SS][2]

    const int tid  = threadIdx.x;
    const int s    = tid >> 8;       // sample within block (0..1)
    const int wg   = tid & 255;      // thread within sample group
    const int wis  = wg >> 5;        // warp within sample group (0..7)
    const int lane = tid & 31;
    const int n    = blockIdx.x * SS + s;

    for (int i = tid; i < SS * DD; i += BLOCK)
        sX[i] = gx[blockIdx.x * SS * DD + i];

    // stage W2 pre-transposed: float4 p = 2*f4+m -> plane m, entry f4:
    // {pk(w0_even,w0_odd), pk(w1_even,w1_odd)} for unit pair 2p,2p+1
    {
        const float4* w2v = (const float4*)gW2;             // [H,2] -> 2048 float4
        for (int p = tid; p < 2 * SW2_U; p += BLOCK) {
            float4 w = w2v[p];
            ulonglong2 e;
            e.x = pk(w.x, w.z);
            e.y = pk(w.y, w.w);
            sW2[((p & 1) << 10) + (p >> 1)] = e;
        }
    }

    // persistent packed state: thread wg owns units 4*f4..4*f4+3, f4 = wg+256*k4
    u64 hp[NP];
    {
        const ulonglong2* b1v = (const ulonglong2*)gb1;
#pragma unroll
        for (int k4 = 0; k4 < NP / 2; k4++) {
            ulonglong2 b = b1v[wg + 256 * k4];
            hp[2*k4+0] = b.x; hp[2*k4+1] = b.y;
        }
    }
    __syncthreads();   // sW2 / sX staged

    for (int ds = 0; ds < DD; ds += 2) {
        if ((ds & 7) == 0) __syncthreads();   // drift control: keep warps within
                                              // a few W1 rows so L1 stays hot
        const float xd0 = sX[s * DD + ds];
        const float xd1 = sX[s * DD + ds + 1];
        const u64 x0p = pk(xd0, xd0);
        const u64 x1p = pk(xd1, xd1);
        const ulonglong2* w1a = (const ulonglong2*)(gW1 + (size_t)ds * HH);
        const ulonglong2* w1b = (const ulonglong2*)(gW1 + (size_t)(ds + 1) * HH);

        u64 p00 = 0ull, p01 = 0ull;   // step ds   dots (packed even/odd)
        u64 p10 = 0ull, p11 = 0ull;   // step ds+1 dots
#pragma unroll
        for (int k4 = 0; k4 < NP / 2; k4++) {
            const int f4 = wg + 256 * k4;
            ulonglong2 wA  = w1a[f4];               // LDG.128, L1-hot
            ulonglong2 wB  = w1b[f4];
            ulonglong2 w2a = sW2[f4];               // m=0, conflict-free LDS.128
            ulonglong2 w2b = sW2[SW2_U + f4];       // m=1
#pragma unroll
            for (int m = 0; m < 2; m++) {
                const int q = 2 * k4 + m;
                const ulonglong2 w2 = m ? w2b : w2a;
                u64 hA = hp[q];
                u64 t0 = (q == 0) ? tanh2_ex2(hA) : tanh2_fma(hA);
                p00 = fma2(t0, w2.x, p00);
                p01 = fma2(t0, w2.y, p01);
                hA = fma2(x0p, m ? wA.y : wA.x, hA);
                u64 t1 = (q == 0) ? tanh2_ex2(hA) : tanh2_fma(hA);
                p10 = fma2(t1, w2.x, p10);
                p11 = fma2(t1, w2.y, p11);
                hp[q] = fma2(x1p, m ? wB.y : wB.x, hA);
            }
        }
        // fold packed accumulators, 3-round butterfly, lanes 0-3 store classes
        float u, v;
        upk(u, v, p00); float a00 = u + v;
        upk(u, v, p01); float a01 = u + v;
        upk(u, v, p10); float a10 = u + v;
        upk(u, v, p11); float a11 = u + v;
#pragma unroll
        for (int off = 16; off >= 4; off >>= 1) {
            a00 += __shfl_xor_sync(0xffffffffu, a00, off);
            a01 += __shfl_xor_sync(0xffffffffu, a01, off);
            a10 += __shfl_xor_sync(0xffffffffu, a10, off);
            a11 += __shfl_xor_sync(0xffffffffu, a11, off);
        }
        if (lane < 4) {
            sPart[((ds    ) * SS + s) * NPW + wis * 4 + lane] = make_float2(a00, a01);
            sPart[((ds + 1) * SS + s) * NPW + wis * 4 + lane] = make_float2(a10, a11);
        }
    }

    // deferred head: threads wg<64 each finish one step d, then product-reduce
    __syncthreads();
    const float b20 = gb2[0], b21 = gb2[1];
    if (wg < DD) {
        const int d = wg;
        float z0 = b20, z1 = b21;
#pragma unroll
        for (int w = 0; w < NPW; w++) {
            float2 v2 = sPart[(d * SS + s) * NPW + w];
            z0 += v2.x; z1 += v2.y;
        }
        float o0 = ftanh(z0), o1 = ftanh(z1);
        float nrm = fmaxf(sqrtf(o0 * o0 + o1 * o1), 1e-12f);
        float sel = (sX[s * DD + d] > 0.0f ? o0 : o1) / nrm;
#pragma unroll
        for (int off = 16; off; off >>= 1)
            sel *= __shfl_xor_sync(0xffffffffu, sel, off);
        if (lane == 0) sProd[s * 2 + wis] = sel;   // wis = 0,1 only (wg<64)
    }
    __syncthreads();
    if (wg == 0) gout[n] = sProd[s * 2 + 0] * sProd[s * 2 + 1];
}

extern "C" void kernel_launch(void* const* d_in, const int* in_sizes, int n_in,
                              void* d_out, int out_size) {
    const float* x  = (const float*)d_in[0];
    const float* W1 = (const float*)d_in[1];
    const float* b1 = (const float*)d_in[2];
    const float* W2 = (const float*)d_in[3];
    const float* b2 = (const float*)d_in[4];
    cudaFuncSetAttribute(qnade_kernel,
                         cudaFuncAttributeMaxDynamicSharedMemorySize, SMEM_BYTES);
    qnade_kernel<<<NN / SS, BLOCK, SMEM_BYTES>>>(x, W1, b1, W2, b2, (float*)d_out);
}

// round 13
// speedup vs baseline: 1.2216x; 1.0144x over previous
#include <cuda_runtime.h>

#define NN    8192
#define DD    64
#define HH    4096
#define SS    2          // samples per block
#define NP    8          // hidden-unit pairs per thread (16 units)
#define BLOCK 512

typedef unsigned long long u64;

static __device__ __forceinline__ u64 pk(float lo, float hi) {
    u64 r; asm("mov.b64 %0,{%1,%2};" : "=l"(r) : "f"(lo), "f"(hi)); return r;
}
static __device__ __forceinline__ void upk(float& lo, float& hi, u64 v) {
    asm("mov.b64 {%0,%1},%2;" : "=f"(lo), "=f"(hi) : "l"(v));
}
static __device__ __forceinline__ u64 fma2(u64 a, u64 b, u64 c) {
    u64 d; asm("fma.rn.f32x2 %0,%1,%2,%3;" : "=l"(d) : "l"(a), "l"(b), "l"(c)); return d;
}
static __device__ __forceinline__ u64 mul2(u64 a, u64 b) {
    u64 d; asm("mul.rn.f32x2 %0,%1,%2;" : "=l"(d) : "l"(a), "l"(b)); return d;
}
static __device__ __forceinline__ u64 add2(u64 a, u64 b) {
    u64 d; asm("add.rn.f32x2 %0,%1,%2;" : "=l"(d) : "l"(a), "l"(b)); return d;
}
static __device__ __forceinline__ float frsq(float x) {
    float r; asm("rsqrt.approx.f32 %0,%1;" : "=f"(r) : "f"(x)); return r;
}
static __device__ __forceinline__ float ftanh(float x) {
    float e = __expf(2.0f * x);
    return 1.0f - __fdividef(2.0f, e + 1.0f);
}
// FMA-path packed tanh: t = s*rsqrt(1+s^2), s = h*P(h^2) (deg-3 sinh Taylor)
static __device__ __forceinline__ u64 tanh2_fma(u64 hA) {
    const u64 C3  = pk(1.98412698e-4f, 1.98412698e-4f);   // 1/7!
    const u64 C2  = pk(8.33333333e-3f, 8.33333333e-3f);   // 1/5!
    const u64 C1  = pk(1.66666667e-1f, 1.66666667e-1f);   // 1/3!
    const u64 ONE = pk(1.0f, 1.0f);
    u64 y = mul2(hA, hA);
    u64 p = fma2(C3, y, C2);
    p = fma2(p, y, C1);
    p = fma2(p, y, ONE);
    u64 sv = mul2(p, hA);
    u64 dd2 = fma2(sv, sv, ONE);
    float dl, dh; upk(dl, dh, dd2);
    return mul2(sv, pk(frsq(dl), frsq(dh)));
}

// smem: packed W2 + packed spins + partials + products (W1 in L1 via LDG)
#define SW2_U 1024                       // ulonglong2 entries per m-plane
#define NPW   32                         // partials per (step, sample)
#define SMEM_BYTES (2*SW2_U*16 + SS*DD*8 + DD*SS*NPW*8 + SS*2*4)

__global__ void __launch_bounds__(BLOCK, 2)
qnade_kernel(const float* __restrict__ gx,  const float* __restrict__ gW1,
             const float* __restrict__ gb1, const float* __restrict__ gW2,
             const float* __restrict__ gb2, float* __restrict__ gout)
{
    extern __shared__ char sm_[];
    ulonglong2* sW2   = (ulonglong2*)sm_;                   // [2][1024] (m-major)
    u64*        sXp   = (u64*)(sW2 + 2 * SW2_U);            // [SS][DD] packed spins
    float2*     sPart = (float2*)(sXp + SS * DD);           // [DD][SS][NPW]
    float*      sProd = (float*)(sPart + DD * SS * NPW);    // [SS][2]

    const int tid  = threadIdx.x;
    const int s    = tid >> 8;       // sample within block (0..1)
    const int wg   = tid & 255;      // thread within sample group
    const int wis  = wg >> 5;        // warp within sample group (0..7)
    const int lane = tid & 31;
    const int n    = blockIdx.x * SS + s;

    for (int i = tid; i < SS * DD; i += BLOCK) {
        float xv = gx[blockIdx.x * SS * DD + i];
        sXp[i] = pk(xv, xv);
    }

    // stage W2 pre-transposed: float4 p = 2*f4+m -> plane m, entry f4:
    // {pk(w0_even,w0_odd), pk(w1_even,w1_odd)} for unit pair 2p,2p+1
    {
        const float4* w2v = (const float4*)gW2;             // [H,2] -> 2048 float4
        for (int p = tid; p < 2 * SW2_U; p += BLOCK) {
            float4 w = w2v[p];
            ulonglong2 e;
            e.x = pk(w.x, w.z);
            e.y = pk(w.y, w.w);
            sW2[((p & 1) << 10) + (p >> 1)] = e;
        }
    }

    // persistent packed state: thread wg owns units 4*f4..4*f4+3, f4 = wg+256*k4
    u64 hp[NP];
    {
        const ulonglong2* b1v = (const ulonglong2*)gb1;
#pragma unroll
        for (int k4 = 0; k4 < NP / 2; k4++) {
            ulonglong2 b = b1v[wg + 256 * k4];
            hp[2*k4+0] = b.x; hp[2*k4+1] = b.y;
        }
    }
    __syncthreads();   // sW2 / sXp staged

    for (int ds = 0; ds < DD; ds += 2) {
        if ((ds & 15) == 0) __syncthreads();  // light drift control for L1
        const u64 x0p = sXp[s * DD + ds];
        const u64 x1p = sXp[s * DD + ds + 1];
        const ulonglong2* w1a = (const ulonglong2*)(gW1 + (size_t)ds * HH);
        const ulonglong2* w1b = (const ulonglong2*)(gW1 + (size_t)(ds + 1) * HH);

        u64 p00 = 0ull, p01 = 0ull;   // step ds   dots (packed even/odd)
        u64 p10 = 0ull, p11 = 0ull;   // step ds+1 dots
#pragma unroll
        for (int k4 = 0; k4 < NP / 2; k4++) {
            const int f4 = wg + 256 * k4;
            ulonglong2 wA  = w1a[f4];               // LDG.128, L1-hot
            ulonglong2 wB  = w1b[f4];
            ulonglong2 w2a = sW2[f4];               // m=0, conflict-free LDS.128
            ulonglong2 w2b = sW2[SW2_U + f4];       // m=1
#pragma unroll
            for (int m = 0; m < 2; m++) {
                const int q = 2 * k4 + m;
                const ulonglong2 w2 = m ? w2b : w2a;
                u64 hA = hp[q];
                u64 t0 = tanh2_fma(hA);
                p00 = fma2(t0, w2.x, p00);
                p01 = fma2(t0, w2.y, p01);
                hA = fma2(x0p, m ? wA.y : wA.x, hA);
                u64 t1 = tanh2_fma(hA);
                p10 = fma2(t1, w2.x, p10);
                p11 = fma2(t1, w2.y, p11);
                hp[q] = fma2(x1p, m ? wB.y : wB.x, hA);
            }
        }
        // fold even/odd halves, repack (col0,col1), packed 3-round butterfly
        float u, v;
        upk(u, v, p00); float a00 = u + v;
        upk(u, v, p01); float a01 = u + v;
        upk(u, v, p10); float a10 = u + v;
        upk(u, v, p11); float a11 = u + v;
        u64 c0 = pk(a00, a01);        // step ds:   (col0, col1)
        u64 c1 = pk(a10, a11);        // step ds+1: (col0, col1)
#pragma unroll
        for (int off = 16; off >= 4; off >>= 1) {
            c0 = add2(c0, __shfl_xor_sync(0xffffffffu, c0, off));
            c1 = add2(c1, __shfl_xor_sync(0xffffffffu, c1, off));
        }
        if (lane < 4) {
            *(u64*)&sPart[((ds    ) * SS + s) * NPW + wis * 4 + lane] = c0;
            *(u64*)&sPart[((ds + 1) * SS + s) * NPW + wis * 4 + lane] = c1;
        }
    }

    // deferred head: threads wg<64 each finish one step d, then product-reduce
    __syncthreads();
    const float b20 = gb2[0], b21 = gb2[1];
    if (wg < DD) {
        const int d = wg;
        float z0 = b20, z1 = b21;
#pragma unroll
        for (int w = 0; w < NPW; w++) {
            float2 v2 = sPart[(d * SS + s) * NPW + w];
            z0 += v2.x; z1 += v2.y;
        }
        float o0 = ftanh(z0), o1 = ftanh(z1);
        float nrm = fmaxf(sqrtf(o0 * o0 + o1 * o1), 1e-12f);
        float xd; { float dum; upk(xd, dum, sXp[s * DD + d]); }
        float sel = (xd > 0.0f ? o0 : o1) / nrm;
#pragma unroll
        for (int off = 16; off; off >>= 1)
            sel *= __shfl_xor_sync(0xffffffffu, sel, off);
        if (lane == 0) sProd[s * 2 + wis] = sel;   // wis = 0,1 only (wg<64)
    }
    __syncthreads();
    if (wg == 0) gout[n] = sProd[s * 2 + 0] * sProd[s * 2 + 1];
}

extern "C" void kernel_launch(void* const* d_in, const int* in_sizes, int n_in,
                              void* d_out, int out_size) {
    const float* x  = (const float*)d_in[0];
    const float* W1 = (const float*)d_in[1];
    const float* b1 = (const float*)d_in[2];
    const float* W2 = (const float*)d_in[3];
    const float* b2 = (const float*)d_in[4];
    cudaFuncSetAttribute(qnade_kernel,
                         cudaFuncAttributeMaxDynamicSharedMemorySize, SMEM_BYTES);
    qnade_kernel<<<NN / SS, BLOCK, SMEM_BYTES>>>(x, W1, b1, W2, b2, (float*)d_out);
}